// round 3
// baseline (speedup 1.0000x reference)
#include <cuda_runtime.h>
#include <cuda_fp16.h>
#include <math.h>

#define NN 50000
#define EE 800000
#define DD 96
#define CC 40
#define NITE 8
#define SMOOTH 0.5f

// Padded transposed-W row stride (floats): 98 keeps LDS.64 phase-pairs conflict-free.
#define WT_STRIDE 98

// ---------------- scratch (device globals; no allocation allowed) ------------
__device__ float  g_h[NN * DD];         // node features (fp32), updated in place
__device__ __half g_support16[NN * DD]; // h @ W_gc, fp16 (gather-only consumer)
__device__ int    g_count[NN];          // per-row edge count
__device__ int    g_rowstart[NN + 1];   // CSR offsets
__device__ int    g_fill[NN];           // fill cursors
__device__ int2   g_edge[EE];           // CSR: {src col, f32 val as int} packed

// packed f32x2 FMA: d.lo += a.lo*b.lo ; d.hi += a.hi*b.hi
__device__ __forceinline__ void ffma2(unsigned long long& d,
                                      unsigned long long a,
                                      unsigned long long b) {
    asm("fma.rn.f32x2 %0, %1, %2, %0;" : "+l"(d) : "l"(a), "l"(b));
}

// ---------------- init: h = x, zero counts ----------------------------------
__global__ void init_kernel(const float* __restrict__ x) {
    int i = blockIdx.x * blockDim.x + threadIdx.x;
    if (i < NN * DD) g_h[i] = x[i];
    if (i < NN) g_count[i] = 0;
}

// ---------------- CSR build --------------------------------------------------
__global__ void hist_kernel(const int* __restrict__ erow) {
    int e = blockIdx.x * blockDim.x + threadIdx.x;
    if (e < EE) atomicAdd(&g_count[erow[e]], 1);
}

__global__ void scan_kernel() {
    __shared__ int part[1024];
    const int CH = (NN + 1023) / 1024;
    int t = threadIdx.x;
    int begin = t * CH;
    int end = begin + CH; if (end > NN) end = NN;
    int s = 0;
    for (int i = begin; i < end; ++i) s += g_count[i];
    part[t] = s;
    __syncthreads();
    for (int off = 1; off < 1024; off <<= 1) {
        int v = (t >= off) ? part[t - off] : 0;
        __syncthreads();
        part[t] += v;
        __syncthreads();
    }
    int running = (t == 0) ? 0 : part[t - 1];
    for (int i = begin; i < end; ++i) {
        g_rowstart[i] = running;
        g_fill[i] = running;
        running += g_count[i];
    }
    if (t == 1023) g_rowstart[NN] = running;  // == EE
}

__global__ void fill_kernel(const int* __restrict__ erow,
                            const int* __restrict__ ecol,
                            const float* __restrict__ ev) {
    int e = blockIdx.x * blockDim.x + threadIdx.x;
    if (e < EE) {
        int r = erow[e];
        int p = atomicAdd(&g_fill[r], 1);
        g_edge[p] = make_int2(ecol[e], __float_as_int(ev[e]));
    }
}

// ---------------- GEMM: support16 = fp16(h @ W_gc) ---------------------------
// 256 threads (8 warps), 64 rows/block, thread = 8 rows x 3 cols.
__global__ void __launch_bounds__(256) gemm_kernel(const float* __restrict__ W) {
    extern __shared__ float smem[];
    float* WsT = smem;                    // [DD cols][WT_STRIDE] transposed W
    float* Hs  = smem + DD * WT_STRIDE;   // [64][DD]
    int lane = threadIdx.x;               // 0..31
    int wy = threadIdx.y;                 // 0..7
    int tid = wy * 32 + lane;
    int row0 = blockIdx.x * 64;

    for (int i = tid; i < DD * DD; i += 256) {
        int k = i / DD, c = i % DD;
        WsT[c * WT_STRIDE + k] = W[i];
    }
    for (int i = tid; i < 64 * DD; i += 256) {
        int r = row0 + i / DD;
        Hs[i] = (r < NN) ? g_h[r * DD + (i % DD)] : 0.f;
    }
    __syncthreads();

    unsigned long long acc[8][3];
#pragma unroll
    for (int i = 0; i < 8; ++i) { acc[i][0] = 0ull; acc[i][1] = 0ull; acc[i][2] = 0ull; }

    const unsigned long long* w0p = (const unsigned long long*)&WsT[(lane)      * WT_STRIDE];
    const unsigned long long* w1p = (const unsigned long long*)&WsT[(lane + 32) * WT_STRIDE];
    const unsigned long long* w2p = (const unsigned long long*)&WsT[(lane + 64) * WT_STRIDE];

#pragma unroll 4
    for (int kk = 0; kk < DD / 2; ++kk) {
        unsigned long long w0 = w0p[kk];
        unsigned long long w1 = w1p[kk];
        unsigned long long w2 = w2p[kk];
#pragma unroll
        for (int i = 0; i < 8; ++i) {
            unsigned long long hv =
                *(const unsigned long long*)&Hs[(wy * 8 + i) * DD + 2 * kk];  // broadcast
            ffma2(acc[i][0], hv, w0);
            ffma2(acc[i][1], hv, w1);
            ffma2(acc[i][2], hv, w2);
        }
    }

#pragma unroll
    for (int i = 0; i < 8; ++i) {
        int r = row0 + wy * 8 + i;
        if (r < NN) {
            float2 a0 = *(float2*)&acc[i][0];
            float2 a1 = *(float2*)&acc[i][1];
            float2 a2 = *(float2*)&acc[i][2];
            g_support16[r * DD + lane]      = __float2half(a0.x + a0.y);
            g_support16[r * DD + lane + 32] = __float2half(a1.x + a1.y);
            g_support16[r * DD + lane + 64] = __float2half(a2.x + a2.y);
        }
    }
}

// ---------------- aggregation + smooth + ReLU (one warp per row) -------------
__global__ void __launch_bounds__(256) agg_kernel(const float* __restrict__ b) {
    int warp = (blockIdx.x * blockDim.x + threadIdx.x) >> 5;
    int lane = threadIdx.x & 31;
    if (warp >= NN) return;
    int j0 = g_rowstart[warp];
    int j1 = g_rowstart[warp + 1];
    float a0 = 0.f, a1 = 0.f, a2 = 0.f;
#pragma unroll 4
    for (int j = j0; j < j1; ++j) {
        int2 e = __ldg(&g_edge[j]);                    // broadcast LDG.64
        float v = __int_as_float(e.y);
        const __half* s = g_support16 + e.x * DD;
        a0 += __half2float(__ldg(&s[lane]))      * v;
        a1 += __half2float(__ldg(&s[lane + 32])) * v;
        a2 += __half2float(__ldg(&s[lane + 64])) * v;
    }
    int base = warp * DD;
    float h0 = g_h[base + lane];
    float h1 = g_h[base + lane + 32];
    float h2 = g_h[base + lane + 64];
    float r0 = SMOOTH * h0 + (1.f - SMOOTH) * (a0 + b[lane]);
    float r1 = SMOOTH * h1 + (1.f - SMOOTH) * (a1 + b[lane + 32]);
    float r2 = SMOOTH * h2 + (1.f - SMOOTH) * (a2 + b[lane + 64]);
    g_h[base + lane]      = fmaxf(r0, 0.f);
    g_h[base + lane + 32] = fmaxf(r1, 0.f);
    g_h[base + lane + 64] = fmaxf(r2, 0.f);
}

// ---------------- final: logits = h @ W_lin, log_softmax ---------------------
__global__ void __launch_bounds__(256) out_kernel(const float* __restrict__ Wl,
                                                  float* __restrict__ out) {
    __shared__ float Ws[DD * CC];
    __shared__ float Hs[32 * DD];
    __shared__ float Ls[32 * CC];
    int tid = threadIdx.x;
    int row0 = blockIdx.x * 32;

    for (int i = tid; i < DD * CC; i += 256) Ws[i] = Wl[i];
    for (int i = tid; i < 32 * DD; i += 256) {
        int r = row0 + i / DD;
        Hs[i] = (r < NN) ? g_h[r * DD + (i % DD)] : 0.f;
    }
    __syncthreads();

    for (int o = tid; o < 32 * CC; o += 256) {
        int r = o / CC, c = o % CC;
        float a = 0.f;
#pragma unroll 4
        for (int k = 0; k < DD; ++k) a += Hs[r * DD + k] * Ws[k * CC + c];
        Ls[o] = a;
    }
    __syncthreads();

    if (tid < 32) {
        int r = row0 + tid;
        if (r < NN) {
            float m = -1e30f;
#pragma unroll
            for (int c = 0; c < CC; ++c) m = fmaxf(m, Ls[tid * CC + c]);
            float s = 0.f;
#pragma unroll
            for (int c = 0; c < CC; ++c) s += expf(Ls[tid * CC + c] - m);
            float lse = m + logf(s);
#pragma unroll
            for (int c = 0; c < CC; ++c) out[r * CC + c] = Ls[tid * CC + c] - lse;
        }
    }
}

// ---------------- launch ------------------------------------------------------
extern "C" void kernel_launch(void* const* d_in, const int* in_sizes, int n_in,
                              void* d_out, int out_size) {
    (void)in_sizes; (void)n_in; (void)out_size;
    const float* x    = (const float*)d_in[0];
    const int*   erow = (const int*)d_in[1];
    const int*   ecol = (const int*)d_in[2];
    const float* ev   = (const float*)d_in[3];
    const float* Wgc  = (const float*)d_in[4];
    const float* bgc  = (const float*)d_in[5];
    const float* Wlin = (const float*)d_in[6];
    float* out = (float*)d_out;

    const int gemm_smem = (DD * WT_STRIDE + 64 * DD) * (int)sizeof(float);  // 62208 B
    cudaFuncSetAttribute(gemm_kernel, cudaFuncAttributeMaxDynamicSharedMemorySize, gemm_smem);

    init_kernel<<<(NN * DD + 255) / 256, 256>>>(x);
    hist_kernel<<<(EE + 255) / 256, 256>>>(erow);
    scan_kernel<<<1, 1024>>>();
    fill_kernel<<<(EE + 255) / 256, 256>>>(erow, ecol, ev);

    for (int it = 0; it < NITE; ++it) {
        gemm_kernel<<<(NN + 63) / 64, dim3(32, 8), gemm_smem>>>(Wgc);
        agg_kernel<<<(NN * 32 + 255) / 256, 256>>>(bgc);
    }

    out_kernel<<<(NN + 31) / 32, 256>>>(Wlin, out);
}

// round 4
// speedup vs baseline: 1.0170x; 1.0170x over previous
#include <cuda_runtime.h>
#include <cuda_fp16.h>
#include <math.h>

#define NN 50000
#define EE 800000
#define DD 96
#define CC 40
#define NITE 8
#define SMOOTH 0.5f

// Padded transposed-W row stride (floats): 98 keeps LDS.64 phase-pairs conflict-free.
#define WT_STRIDE 98

// ---------------- scratch (device globals; no allocation allowed) ------------
__device__ float  g_h[NN * DD];         // node features (fp32), updated in place
__device__ __half g_support16[NN * DD]; // h @ W_gc, fp16 (gather-only consumer)
__device__ int    g_count[NN];          // per-row edge count
__device__ int    g_rowstart[NN + 1];   // CSR offsets
__device__ int    g_fill[NN];           // fill cursors
__device__ int2   g_edge[EE];           // CSR: {src col, f32 val as int} packed

// packed f32x2 FMA: d.lo += a.lo*b.lo ; d.hi += a.hi*b.hi
__device__ __forceinline__ void ffma2(unsigned long long& d,
                                      unsigned long long a,
                                      unsigned long long b) {
    asm("fma.rn.f32x2 %0, %1, %2, %0;" : "+l"(d) : "l"(a), "l"(b));
}
__device__ __forceinline__ void ffma2f(float2& d, float2 a, float2 b) {
    unsigned long long dd = *(unsigned long long*)&d;
    asm("fma.rn.f32x2 %0, %1, %2, %0;"
        : "+l"(dd) : "l"(*(unsigned long long*)&a), "l"(*(unsigned long long*)&b));
    d = *(float2*)&dd;
}

// ---------------- init: h = x, zero counts ----------------------------------
__global__ void init_kernel(const float* __restrict__ x) {
    int i = blockIdx.x * blockDim.x + threadIdx.x;
    if (i < NN * DD) g_h[i] = x[i];
    if (i < NN) g_count[i] = 0;
}

// ---------------- CSR build --------------------------------------------------
__global__ void hist_kernel(const int* __restrict__ erow) {
    int e = blockIdx.x * blockDim.x + threadIdx.x;
    if (e < EE) atomicAdd(&g_count[erow[e]], 1);
}

__global__ void scan_kernel() {
    __shared__ int part[1024];
    const int CH = (NN + 1023) / 1024;
    int t = threadIdx.x;
    int begin = t * CH;
    int end = begin + CH; if (end > NN) end = NN;
    int s = 0;
    for (int i = begin; i < end; ++i) s += g_count[i];
    part[t] = s;
    __syncthreads();
    for (int off = 1; off < 1024; off <<= 1) {
        int v = (t >= off) ? part[t - off] : 0;
        __syncthreads();
        part[t] += v;
        __syncthreads();
    }
    int running = (t == 0) ? 0 : part[t - 1];
    for (int i = begin; i < end; ++i) {
        g_rowstart[i] = running;
        g_fill[i] = running;
        running += g_count[i];
    }
    if (t == 1023) g_rowstart[NN] = running;  // == EE
}

__global__ void fill_kernel(const int* __restrict__ erow,
                            const int* __restrict__ ecol,
                            const float* __restrict__ ev) {
    int e = blockIdx.x * blockDim.x + threadIdx.x;
    if (e < EE) {
        int r = erow[e];
        int p = atomicAdd(&g_fill[r], 1);
        g_edge[p] = make_int2(ecol[e], __float_as_int(ev[e]));
    }
}

// ---------------- GEMM: support16 = fp16(h @ W_gc) ---------------------------
// 256 threads (8 warps), 64 rows/block, thread = 8 rows x 3 cols, FFMA2.
__global__ void __launch_bounds__(256) gemm_kernel(const float* __restrict__ W) {
    extern __shared__ float smem[];
    float* WsT = smem;                    // [DD cols][WT_STRIDE] transposed W
    float* Hs  = smem + DD * WT_STRIDE;   // [64][DD]
    int lane = threadIdx.x;               // 0..31
    int wy = threadIdx.y;                 // 0..7
    int tid = wy * 32 + lane;
    int row0 = blockIdx.x * 64;

    for (int i = tid; i < DD * DD; i += 256) {
        int k = i / DD, c = i % DD;
        WsT[c * WT_STRIDE + k] = W[i];
    }
    for (int i = tid; i < 64 * DD; i += 256) {
        int r = row0 + i / DD;
        Hs[i] = (r < NN) ? g_h[r * DD + (i % DD)] : 0.f;
    }
    __syncthreads();

    unsigned long long acc[8][3];
#pragma unroll
    for (int i = 0; i < 8; ++i) { acc[i][0] = 0ull; acc[i][1] = 0ull; acc[i][2] = 0ull; }

    const unsigned long long* w0p = (const unsigned long long*)&WsT[(lane)      * WT_STRIDE];
    const unsigned long long* w1p = (const unsigned long long*)&WsT[(lane + 32) * WT_STRIDE];
    const unsigned long long* w2p = (const unsigned long long*)&WsT[(lane + 64) * WT_STRIDE];

#pragma unroll 4
    for (int kk = 0; kk < DD / 2; ++kk) {
        unsigned long long w0 = w0p[kk];
        unsigned long long w1 = w1p[kk];
        unsigned long long w2 = w2p[kk];
#pragma unroll
        for (int i = 0; i < 8; ++i) {
            unsigned long long hv =
                *(const unsigned long long*)&Hs[(wy * 8 + i) * DD + 2 * kk];  // broadcast
            ffma2(acc[i][0], hv, w0);
            ffma2(acc[i][1], hv, w1);
            ffma2(acc[i][2], hv, w2);
        }
    }

#pragma unroll
    for (int i = 0; i < 8; ++i) {
        int r = row0 + wy * 8 + i;
        if (r < NN) {
            float2 a0 = *(float2*)&acc[i][0];
            float2 a1 = *(float2*)&acc[i][1];
            float2 a2 = *(float2*)&acc[i][2];
            g_support16[r * DD + lane]      = __float2half(a0.x + a0.y);
            g_support16[r * DD + lane + 32] = __float2half(a1.x + a1.y);
            g_support16[r * DD + lane + 64] = __float2half(a2.x + a2.y);
        }
    }
}

// ---------------- aggregation + smooth + ReLU --------------------------------
// One warp per row. 4 edge-groups x 8 feature-owner lanes.
// Each lane owns 12 features (3 x uint2 = 3 x 4 halves); per 4 edges the warp
// issues 1 meta LDG.64 + 3 data LDG.64 (vs 16 LDGs in the scalar version).
__global__ void __launch_bounds__(256) agg_kernel(const float* __restrict__ b) {
    int warp = (blockIdx.x * blockDim.x + threadIdx.x) >> 5;
    int lane = threadIdx.x & 31;
    if (warp >= NN) return;
    int grp = lane >> 3;   // 0..3: which edge of the 4-batch
    int sub = lane & 7;    // 0..7: which feature quad-group

    int j0 = g_rowstart[warp];
    int j1 = g_rowstart[warp + 1];

    float2 acc[6];
#pragma unroll
    for (int i = 0; i < 6; ++i) acc[i] = make_float2(0.f, 0.f);

    for (int j = j0 + grp; j < j1; j += 4) {
        int2 e = __ldg(&g_edge[j]);
        float v = __int_as_float(e.y);
        float2 vv = make_float2(v, v);
        const uint2* s = (const uint2*)(g_support16 + (size_t)e.x * DD);  // 24 uint2/row
        uint2 d0 = __ldg(&s[sub]);        // features 4*sub      .. +3
        uint2 d1 = __ldg(&s[8 + sub]);    // features 32 + 4*sub .. +3
        uint2 d2 = __ldg(&s[16 + sub]);   // features 64 + 4*sub .. +3
        float2 f;
        f = __half22float2(*(__half2*)&d0.x); ffma2f(acc[0], f, vv);
        f = __half22float2(*(__half2*)&d0.y); ffma2f(acc[1], f, vv);
        f = __half22float2(*(__half2*)&d1.x); ffma2f(acc[2], f, vv);
        f = __half22float2(*(__half2*)&d1.y); ffma2f(acc[3], f, vv);
        f = __half22float2(*(__half2*)&d2.x); ffma2f(acc[4], f, vv);
        f = __half22float2(*(__half2*)&d2.y); ffma2f(acc[5], f, vv);
    }

    // fold the 4 edge-groups (lanes sub, sub+8, sub+16, sub+24)
#pragma unroll
    for (int i = 0; i < 6; ++i) {
        acc[i].x += __shfl_xor_sync(0xffffffffu, acc[i].x, 8);
        acc[i].y += __shfl_xor_sync(0xffffffffu, acc[i].y, 8);
        acc[i].x += __shfl_xor_sync(0xffffffffu, acc[i].x, 16);
        acc[i].y += __shfl_xor_sync(0xffffffffu, acc[i].y, 16);
    }

    if (lane < 8) {
        float* hrow = g_h + (size_t)warp * DD;
#pragma unroll
        for (int sg = 0; sg < 3; ++sg) {
            int off = sg * 32 + sub * 4;
            float4 hv = *(float4*)&hrow[off];
            float4 bv = *(const float4*)&b[off];
            float2 a0 = acc[2 * sg];
            float2 a1 = acc[2 * sg + 1];
            hv.x = fmaxf(SMOOTH * hv.x + (1.f - SMOOTH) * (a0.x + bv.x), 0.f);
            hv.y = fmaxf(SMOOTH * hv.y + (1.f - SMOOTH) * (a0.y + bv.y), 0.f);
            hv.z = fmaxf(SMOOTH * hv.z + (1.f - SMOOTH) * (a1.x + bv.z), 0.f);
            hv.w = fmaxf(SMOOTH * hv.w + (1.f - SMOOTH) * (a1.y + bv.w), 0.f);
            *(float4*)&hrow[off] = hv;
        }
    }
}

// ---------------- final: logits = h @ W_lin, log_softmax ---------------------
__global__ void __launch_bounds__(256) out_kernel(const float* __restrict__ Wl,
                                                  float* __restrict__ out) {
    __shared__ float Ws[DD * CC];
    __shared__ float Hs[32 * DD];
    __shared__ float Ls[32 * CC];
    int tid = threadIdx.x;
    int row0 = blockIdx.x * 32;

    for (int i = tid; i < DD * CC; i += 256) Ws[i] = Wl[i];
    for (int i = tid; i < 32 * DD; i += 256) {
        int r = row0 + i / DD;
        Hs[i] = (r < NN) ? g_h[r * DD + (i % DD)] : 0.f;
    }
    __syncthreads();

    for (int o = tid; o < 32 * CC; o += 256) {
        int r = o / CC, c = o % CC;
        float a = 0.f;
#pragma unroll 4
        for (int k = 0; k < DD; ++k) a += Hs[r * DD + k] * Ws[k * CC + c];
        Ls[o] = a;
    }
    __syncthreads();

    if (tid < 32) {
        int r = row0 + tid;
        if (r < NN) {
            float m = -1e30f;
#pragma unroll
            for (int c = 0; c < CC; ++c) m = fmaxf(m, Ls[tid * CC + c]);
            float s = 0.f;
#pragma unroll
            for (int c = 0; c < CC; ++c) s += expf(Ls[tid * CC + c] - m);
            float lse = m + logf(s);
#pragma unroll
            for (int c = 0; c < CC; ++c) out[r * CC + c] = Ls[tid * CC + c] - lse;
        }
    }
}

// ---------------- launch ------------------------------------------------------
extern "C" void kernel_launch(void* const* d_in, const int* in_sizes, int n_in,
                              void* d_out, int out_size) {
    (void)in_sizes; (void)n_in; (void)out_size;
    const float* x    = (const float*)d_in[0];
    const int*   erow = (const int*)d_in[1];
    const int*   ecol = (const int*)d_in[2];
    const float* ev   = (const float*)d_in[3];
    const float* Wgc  = (const float*)d_in[4];
    const float* bgc  = (const float*)d_in[5];
    const float* Wlin = (const float*)d_in[6];
    float* out = (float*)d_out;

    const int gemm_smem = (DD * WT_STRIDE + 64 * DD) * (int)sizeof(float);  // 62208 B
    cudaFuncSetAttribute(gemm_kernel, cudaFuncAttributeMaxDynamicSharedMemorySize, gemm_smem);

    init_kernel<<<(NN * DD + 255) / 256, 256>>>(x);
    hist_kernel<<<(EE + 255) / 256, 256>>>(erow);
    scan_kernel<<<1, 1024>>>();
    fill_kernel<<<(EE + 255) / 256, 256>>>(erow, ecol, ev);

    for (int it = 0; it < NITE; ++it) {
        gemm_kernel<<<(NN + 63) / 64, dim3(32, 8), gemm_smem>>>(Wgc);
        agg_kernel<<<(NN * 32 + 255) / 256, 256>>>(bgc);
    }

    out_kernel<<<(NN + 31) / 32, 256>>>(Wlin, out);
}

// round 5
// speedup vs baseline: 1.4629x; 1.4385x over previous
#include <cuda_runtime.h>
#include <cuda_fp16.h>
#include <math.h>
#include <mma.h>
using namespace nvcuda;

#define NN 50000
#define EE 800000
#define DD 96
#define CC 40
#define NITE 8
#define SMOOTH 0.5f

#define MROWS 128
#define GBLOCKS ((NN + MROWS - 1) / MROWS)   // 391
#define LDW 104   // padded half ld for W smem (conflict-free LDSM)
#define LDO 104   // padded float ld for output smem

// ---------------- scratch (device globals; no allocation allowed) ------------
__device__ float  g_h[NN * DD];                    // fp32 master features
__device__ __half g_h16[(GBLOCKS * MROWS) * DD];   // fp16 mirror (padded tail, zero-init)
__device__ __half g_W16[DD * DD];                  // fp16 W_gc
__device__ __half g_support16[NN * DD];            // GEMM out / agg in
__device__ int    g_count[NN];
__device__ int    g_rowstart[NN + 1];
__device__ int    g_fill[NN];
__device__ int2   g_edge[EE];                      // CSR: {src col, f32 val}

// packed f32x2 FMA
__device__ __forceinline__ void ffma2f(float2& d, float2 a, float2 b) {
    unsigned long long dd = *(unsigned long long*)&d;
    asm("fma.rn.f32x2 %0, %1, %2, %0;"
        : "+l"(dd) : "l"(*(unsigned long long*)&a), "l"(*(unsigned long long*)&b));
    d = *(float2*)&dd;
}

// ---------------- init: h = x (fp32+fp16), W16, zero counts ------------------
__global__ void init_kernel(const float* __restrict__ x, const float* __restrict__ W) {
    int i = blockIdx.x * blockDim.x + threadIdx.x;
    if (i < NN * DD) { float v = x[i]; g_h[i] = v; g_h16[i] = __float2half(v); }
    if (i < DD * DD) g_W16[i] = __float2half(W[i]);
    if (i < NN) g_count[i] = 0;
}

// ---------------- CSR build --------------------------------------------------
__global__ void hist_kernel(const int* __restrict__ erow) {
    int e = blockIdx.x * blockDim.x + threadIdx.x;
    if (e < EE) atomicAdd(&g_count[erow[e]], 1);
}

__global__ void scan_kernel() {
    __shared__ int part[1024];
    const int CH = (NN + 1023) / 1024;
    int t = threadIdx.x;
    int begin = t * CH;
    int end = begin + CH; if (end > NN) end = NN;
    int s = 0;
    for (int i = begin; i < end; ++i) s += g_count[i];
    part[t] = s;
    __syncthreads();
    for (int off = 1; off < 1024; off <<= 1) {
        int v = (t >= off) ? part[t - off] : 0;
        __syncthreads();
        part[t] += v;
        __syncthreads();
    }
    int running = (t == 0) ? 0 : part[t - 1];
    for (int i = begin; i < end; ++i) {
        g_rowstart[i] = running;
        g_fill[i] = running;
        running += g_count[i];
    }
    if (t == 1023) g_rowstart[NN] = running;  // == EE
}

__global__ void fill_kernel(const int* __restrict__ erow,
                            const int* __restrict__ ecol,
                            const float* __restrict__ ev) {
    int e = blockIdx.x * blockDim.x + threadIdx.x;
    if (e < EE) {
        int r = erow[e];
        int p = atomicAdd(&g_fill[r], 1);
        g_edge[p] = make_int2(ecol[e], __float_as_int(ev[e]));
    }
}

// ---------------- GEMM: support16 = fp16(h16 @ W16), tensor cores ------------
// 256 threads = 8 warps; warp = one 16-row band of a 128-row block.
// A frags straight from global (L2-resident h16); B = W16 staged in smem.
__global__ void __launch_bounds__(256) gemm_kernel() {
    extern __shared__ char sm[];
    __half* Ws = (__half*)sm;                                   // [DD][LDW]
    float*  Os = (float*)(sm + DD * LDW * sizeof(__half));      // [MROWS][LDO]
    int tid = threadIdx.x, wid = tid >> 5, lane = tid & 31;
    int row0 = blockIdx.x * MROWS;

    // stage W16 (row-major k x n, padded)
    for (int i = tid; i < DD * DD / 8; i += 256) {
        int r = (i * 8) / DD, c = (i * 8) % DD;
        *(uint4*)&Ws[r * LDW + c] = *(const uint4*)&g_W16[r * DD + c];
    }
    __syncthreads();

    wmma::fragment<wmma::accumulator, 16, 16, 16, float> acc[6];
#pragma unroll
    for (int n = 0; n < 6; ++n) wmma::fill_fragment(acc[n], 0.f);

    const __half* Abase = g_h16 + (size_t)(row0 + wid * 16) * DD;
#pragma unroll
    for (int k = 0; k < 6; ++k) {
        wmma::fragment<wmma::matrix_a, 16, 16, 16, __half, wmma::row_major> af;
        wmma::load_matrix_sync(af, Abase + k * 16, DD);
#pragma unroll
        for (int n = 0; n < 6; ++n) {
            wmma::fragment<wmma::matrix_b, 16, 16, 16, __half, wmma::row_major> bf;
            wmma::load_matrix_sync(bf, Ws + (k * 16) * LDW + n * 16, LDW);
            wmma::mma_sync(acc[n], af, bf, acc[n]);
        }
    }

    float* Oband = Os + wid * 16 * LDO;
#pragma unroll
    for (int n = 0; n < 6; ++n)
        wmma::store_matrix_sync(Oband + n * 16, acc[n], LDO, wmma::mem_row_major);
    __syncwarp();

    // convert band to fp16 and store (row guard for the 50048-row padding)
#pragma unroll
    for (int t = 0; t < 12; ++t) {
        int idx = lane + 32 * t;            // 0..383 : 16 rows x 24 float4
        int r = idx / 24, c4 = idx % 24;
        int grow = row0 + wid * 16 + r;
        if (grow < NN) {
            float4 v = *(float4*)&Oband[r * LDO + c4 * 4];
            __half2 h0 = __floats2half2_rn(v.x, v.y);
            __half2 h1 = __floats2half2_rn(v.z, v.w);
            uint2 u; u.x = *(unsigned*)&h0; u.y = *(unsigned*)&h1;
            *(uint2*)&g_support16[(size_t)grow * DD + c4 * 4] = u;
        }
    }
}

// ---------------- aggregation + smooth + ReLU --------------------------------
// One warp per row; 4 edge-groups x 8 feature-owner lanes (R4 layout).
// Epilogue now also refreshes the fp16 mirror g_h16.
__global__ void __launch_bounds__(256) agg_kernel(const float* __restrict__ b) {
    int warp = (blockIdx.x * blockDim.x + threadIdx.x) >> 5;
    int lane = threadIdx.x & 31;
    if (warp >= NN) return;
    int grp = lane >> 3;
    int sub = lane & 7;

    int j0 = g_rowstart[warp];
    int j1 = g_rowstart[warp + 1];

    float2 acc[6];
#pragma unroll
    for (int i = 0; i < 6; ++i) acc[i] = make_float2(0.f, 0.f);

    for (int j = j0 + grp; j < j1; j += 4) {
        int2 e = __ldg(&g_edge[j]);
        float v = __int_as_float(e.y);
        float2 vv = make_float2(v, v);
        const uint2* s = (const uint2*)(g_support16 + (size_t)e.x * DD);
        uint2 d0 = __ldg(&s[sub]);
        uint2 d1 = __ldg(&s[8 + sub]);
        uint2 d2 = __ldg(&s[16 + sub]);
        float2 f;
        f = __half22float2(*(__half2*)&d0.x); ffma2f(acc[0], f, vv);
        f = __half22float2(*(__half2*)&d0.y); ffma2f(acc[1], f, vv);
        f = __half22float2(*(__half2*)&d1.x); ffma2f(acc[2], f, vv);
        f = __half22float2(*(__half2*)&d1.y); ffma2f(acc[3], f, vv);
        f = __half22float2(*(__half2*)&d2.x); ffma2f(acc[4], f, vv);
        f = __half22float2(*(__half2*)&d2.y); ffma2f(acc[5], f, vv);
    }

#pragma unroll
    for (int i = 0; i < 6; ++i) {
        acc[i].x += __shfl_xor_sync(0xffffffffu, acc[i].x, 8);
        acc[i].y += __shfl_xor_sync(0xffffffffu, acc[i].y, 8);
        acc[i].x += __shfl_xor_sync(0xffffffffu, acc[i].x, 16);
        acc[i].y += __shfl_xor_sync(0xffffffffu, acc[i].y, 16);
    }

    if (lane < 8) {
        float* hrow = g_h + (size_t)warp * DD;
#pragma unroll
        for (int sg = 0; sg < 3; ++sg) {
            int off = sg * 32 + sub * 4;
            float4 hv = *(float4*)&hrow[off];
            float4 bv = *(const float4*)&b[off];
            float2 a0 = acc[2 * sg];
            float2 a1 = acc[2 * sg + 1];
            hv.x = fmaxf(SMOOTH * hv.x + (1.f - SMOOTH) * (a0.x + bv.x), 0.f);
            hv.y = fmaxf(SMOOTH * hv.y + (1.f - SMOOTH) * (a0.y + bv.y), 0.f);
            hv.z = fmaxf(SMOOTH * hv.z + (1.f - SMOOTH) * (a1.x + bv.z), 0.f);
            hv.w = fmaxf(SMOOTH * hv.w + (1.f - SMOOTH) * (a1.y + bv.w), 0.f);
            *(float4*)&hrow[off] = hv;
            __half2 p0 = __floats2half2_rn(hv.x, hv.y);
            __half2 p1 = __floats2half2_rn(hv.z, hv.w);
            uint2 u; u.x = *(unsigned*)&p0; u.y = *(unsigned*)&p1;
            *(uint2*)&g_h16[(size_t)warp * DD + off] = u;
        }
    }
}

// ---------------- final: logits = h @ W_lin, log_softmax ---------------------
__global__ void __launch_bounds__(256) out_kernel(const float* __restrict__ Wl,
                                                  float* __restrict__ out) {
    __shared__ float Ws2[DD * CC];
    __shared__ float Hs[32 * DD];
    __shared__ float Ls[32 * CC];
    int tid = threadIdx.x;
    int row0 = blockIdx.x * 32;

    for (int i = tid; i < DD * CC; i += 256) Ws2[i] = Wl[i];
    for (int i = tid; i < 32 * DD; i += 256) {
        int r = row0 + i / DD;
        Hs[i] = (r < NN) ? g_h[r * DD + (i % DD)] : 0.f;
    }
    __syncthreads();

    for (int o = tid; o < 32 * CC; o += 256) {
        int r = o / CC, c = o % CC;
        float a = 0.f;
#pragma unroll 4
        for (int k = 0; k < DD; ++k) a += Hs[r * DD + k] * Ws2[k * CC + c];
        Ls[o] = a;
    }
    __syncthreads();

    if (tid < 32) {
        int r = row0 + tid;
        if (r < NN) {
            float m = -1e30f;
#pragma unroll
            for (int c = 0; c < CC; ++c) m = fmaxf(m, Ls[tid * CC + c]);
            float s = 0.f;
#pragma unroll
            for (int c = 0; c < CC; ++c) s += expf(Ls[tid * CC + c] - m);
            float lse = m + logf(s);
#pragma unroll
            for (int c = 0; c < CC; ++c) out[r * CC + c] = Ls[tid * CC + c] - lse;
        }
    }
}

// ---------------- launch ------------------------------------------------------
extern "C" void kernel_launch(void* const* d_in, const int* in_sizes, int n_in,
                              void* d_out, int out_size) {
    (void)in_sizes; (void)n_in; (void)out_size;
    const float* x    = (const float*)d_in[0];
    const int*   erow = (const int*)d_in[1];
    const int*   ecol = (const int*)d_in[2];
    const float* ev   = (const float*)d_in[3];
    const float* Wgc  = (const float*)d_in[4];
    const float* bgc  = (const float*)d_in[5];
    const float* Wlin = (const float*)d_in[6];
    float* out = (float*)d_out;

    const int gemm_smem = DD * LDW * (int)sizeof(__half)
                        + MROWS * LDO * (int)sizeof(float);   // 19968 + 53248 = 73216 B
    cudaFuncSetAttribute(gemm_kernel, cudaFuncAttributeMaxDynamicSharedMemorySize, gemm_smem);

    init_kernel<<<(NN * DD + 255) / 256, 256>>>(x, Wgc);
    hist_kernel<<<(EE + 255) / 256, 256>>>(erow);
    scan_kernel<<<1, 1024>>>();
    fill_kernel<<<(EE + 255) / 256, 256>>>(erow, ecol, ev);

    for (int it = 0; it < NITE; ++it) {
        gemm_kernel<<<GBLOCKS, 256, gemm_smem>>>();
        agg_kernel<<<(NN * 32 + 255) / 256, 256>>>(bgc);
    }

    out_kernel<<<(NN + 31) / 32, 256>>>(Wlin, out);
}